// round 16
// baseline (speedup 1.0000x reference)
#include <cuda_runtime.h>
#include <cooperative_groups.h>
#include <cuda_bf16.h>
#include <stdint.h>

namespace cg = cooperative_groups;

#define T_STEPS  2000
#define BATCH    512
#define CLUSTER_N 4
#define NCLUSTERS 32
#define THREADS  512
#define BC       16      // batch rows per cluster (2 streams of 8)
#define PSTR     132     // partial row stride (words): conflict-free STS/LDS

typedef unsigned long long ull;

// layer0 hidden sequence as packed words (bf16 hi | bf16 lo << 16)
__device__ unsigned g_h1[(size_t)T_STEPS * BATCH * 128];
__device__ float    g_h2last[BATCH * 128];

// ---------- activations ----------
__device__ __forceinline__ float tanh_f(float x){float y;asm("tanh.approx.f32 %0,%1;":"=f"(y):"f"(x));return y;}
__device__ __forceinline__ float sig_f(float x){ return 0.5f*tanh_f(0.5f*x) + 0.5f; }

// ---------- mbarrier / cluster helpers ----------
__device__ __forceinline__ void mbar_init(unsigned a, unsigned cnt) {
    asm volatile("mbarrier.init.shared.b64 [%0], %1;" :: "r"(a), "r"(cnt) : "memory");
}
__device__ __forceinline__ void mbar_arrive_rank(unsigned a, unsigned rk) {
    asm volatile(
        "{\n\t.reg .b32 ra;\n\t"
        "mapa.shared::cluster.u32 ra, %0, %1;\n\t"
        "mbarrier.arrive.release.cluster.shared::cluster.b64 _, [ra];\n\t}"
        :: "r"(a), "r"(rk) : "memory");
}
__device__ __forceinline__ void mbar_wait_cl(unsigned a, unsigned par) {
    asm volatile(
        "{\n\t.reg .pred P;\n\tLW%=:\n\t"
        "mbarrier.try_wait.parity.acquire.cluster.shared::cta.b64 P, [%0], %1, 0x989680;\n\t"
        "@P bra LD%=;\n\tbra LW%=;\n\tLD%=:\n\t}"
        :: "r"(a), "r"(par) : "memory");
}
__device__ __forceinline__ unsigned mapa_rk(unsigned a, unsigned rk) {
    unsigned r; asm("mapa.shared::cluster.u32 %0, %1, %2;" : "=r"(r) : "r"(a), "r"(rk));
    return r;
}
__device__ __forceinline__ void stc_u32(unsigned a, unsigned v) {
    asm volatile("st.shared::cluster.u32 [%0], %1;" :: "r"(a), "r"(v) : "memory");
}

// ---------- bf16 HMMA m16n8k16 ----------
__device__ __forceinline__ void mma_bf16(float* d, const unsigned* a, const unsigned* b) {
    asm volatile(
        "mma.sync.aligned.m16n8k16.row.col.f32.bf16.bf16.f32 "
        "{%0,%1,%2,%3}, {%4,%5,%6,%7}, {%8,%9}, {%0,%1,%2,%3};"
        : "+f"(d[0]), "+f"(d[1]), "+f"(d[2]), "+f"(d[3])
        : "r"(a[0]), "r"(a[1]), "r"(a[2]), "r"(a[3]), "r"(b[0]), "r"(b[1]));
}
__device__ __forceinline__ unsigned pack2(float x, float y) {
    __nv_bfloat162 v = __floats2bfloat162_rn(x, y);
    return *reinterpret_cast<unsigned*>(&v);
}
__device__ __forceinline__ unsigned pack_hilo(float v) {
    __nv_bfloat16 hb = __float2bfloat16(v);
    float hf = __bfloat162float(hb);
    __nv_bfloat16 lb = __float2bfloat16(v - hf);
    return (unsigned)__bfloat16_as_ushort(hb) | ((unsigned)__bfloat16_as_ushort(lb) << 16);
}

// =====================================================================
// Two-stream deferred-rendezvous persistent LSTM scan.
// Cluster of 4 CTAs = 16 batch rows = 2 independent streams of 8 rows.
// Phase phi = 2t + s processes stream s at step t. The cluster wait for
// stream s (h(t) replicated) is deferred one full phase: arrivals happen
// at phase(t-1,s); phase(t-1,s^1) runs in between -> rendezvous settles
// off the critical path. Stream-private mbarriers (count=32: lane0 of
// warps 0-7 of each of 4 CTAs release-arrives on every peer).
// CTA rank r owns gate-interleaved cols [32r,32r+32) of every gate ->
// pointwise fully CTA-local; h pushed to peers as ONE packed u32 word.
// B row layout (u32 words): [h p0:128][h p1:128][in p0:IN_W][in p1:IN_W]
// GEMM: D[128][8] bf16 HMMA m16n8k16, 3-pass split precision
// (Whi*hhi + Whi*hlo + Wlo*hhi), A step-invariant in registers.
// 16 warps = 4 m-pairs x 4 K-quarters; partials (single buffer per
// stream) combined in the pointwise pass.
// =====================================================================
template<int K_IN, int K_PAD, int KS, bool IS_L0>
__global__ __launch_bounds__(THREADS, 1) __cluster_dims__(CLUSTER_N, 1, 1)
void lstm_scan(const float* __restrict__ W_ih, const float* __restrict__ W_hh,
               const float* __restrict__ b_ih, const float* __restrict__ b_hh,
               const float* __restrict__ x)
{
    constexpr int IN_W  = K_PAD - 128;
    constexpr int RW    = 256 + 2 * IN_W;          // words per B row
    constexpr int ROWB  = RW * 4 + 16;             // bytes per B row
    constexpr int PHALF = 32 * PSTR;               // partial words per stream
    constexpr int OPART = BC * ROWB;
    constexpr int OBIAS = OPART + 2 * PHALF * 4;
    constexpr int OMB   = OBIAS + 512;

    extern __shared__ char smraw[];
    char* base = (char*)(((uintptr_t)smraw + 127) & ~(uintptr_t)127);
    float* part   = (float*)(base + OPART);
    float* bias_s = (float*)(base + OBIAS);
    const unsigned base_u = (unsigned)__cvta_generic_to_shared(base);
    const unsigned mb_u   = base_u + OMB;          // two mbarriers (8B apart)

    cg::cluster_group cluster = cg::this_cluster();
    const int rank = (int)cluster.block_rank();
    const int tid  = threadIdx.x;
    const int warp = tid >> 5, lane = tid & 31;
    const int lg = lane >> 2, la = lane & 3;
    const int mtp = warp & 3, kq = warp >> 2;
    const int cid = blockIdx.x / CLUSTER_N;
    const int B0  = cid * BC;

    // ---- one-time: weight fragments (hi/lo) into registers ----
    unsigned Ahi[2][KS][4], Alo[2][KS][4];
    #pragma unroll
    for (int mt = 0; mt < 2; ++mt) {
        const int MT = mtp * 2 + mt;
        #pragma unroll
        for (int s = 0; s < KS; ++s) {
            const int kbase = (kq * KS + s) * 16;
            #pragma unroll
            for (int r = 0; r < 4; ++r) {
                int m = MT * 16 + lg + ((r & 1) ? 8 : 0);
                int k = kbase + la * 2 + ((r & 2) ? 8 : 0);
                int grow = (m >> 5) * 128 + 32 * rank + (m & 31);
                float v0 = 0.0f, v1 = 0.0f;
                if (k < 128) v0 = W_hh[grow * 128 + k];
                else if (k - 128 < K_IN) v0 = W_ih[grow * K_IN + (k - 128)];
                if (k + 1 < 128) v1 = W_hh[grow * 128 + k + 1];
                else if (k + 1 - 128 < K_IN) v1 = W_ih[grow * K_IN + (k + 1 - 128)];
                float h0 = __bfloat162float(__float2bfloat16(v0));
                float h1 = __bfloat162float(__float2bfloat16(v1));
                Ahi[mt][s][r] = pack2(h0, h1);
                Alo[mt][s][r] = pack2(v0 - h0, v1 - h1);
            }
        }
    }

    // zero the whole B tile (h(0)=0, unused input words stay 0)
    for (int i = tid * 4; i < BC * ROWB; i += THREADS * 4)
        *(unsigned*)(base + i) = 0u;
    if (tid < 128) {
        int g = tid >> 5, c = tid & 31;
        bias_s[tid] = b_ih[g * 128 + 32 * rank + c] + b_hh[g * 128 + 32 * rank + c];
    }
    if (tid == 0) { mbar_init(mb_u, 32); mbar_init(mb_u + 8, 32); }
    __syncthreads();

    unsigned peer_base[CLUSTER_N];
    #pragma unroll
    for (int d = 0; d < CLUSTER_N; ++d) peer_base[d] = mapa_rk(base_u, d);

    // pointwise (warps 0-7): stream row = warp, col = lane
    float creg[2] = {0.0f, 0.0f};
    const float bi0 = bias_s[lane], bi1 = bias_s[32 + lane],
                bi2 = bias_s[64 + lane], bi3 = bias_s[96 + lane];

    // staging (warps 8-15): u in [0,256)
    const int u = tid - 256;
    int srow = 0, scol = 0;
    if constexpr (IS_L0) { if (u >= 0) { srow = u / 13; scol = u - srow * 13; } }
    else                 { if (u >= 0) { srow = u >> 5; scol = (u & 31) * 4; } }

    float pf_f[2] = {0.0f, 0.0f};
    uint4 pf_u[2] = {{0,0,0,0},{0,0,0,0}};
    auto prefetch = [&](int s, int t) {            // warps 8-15
        if constexpr (IS_L0) {
            if (u < BC / 2 * 13)
                pf_f[s] = x[((size_t)(B0 + s * 8 + srow) * T_STEPS + t) * 13 + scol];
        } else {
            pf_u[s] = *(const uint4*)&g_h1[((size_t)t * BATCH + B0 + s * 8 + srow) * 128 + scol];
        }
    };
    auto stage = [&](int s, int pb) {              // warps 8-15; writes parity pb
        char* dst = base + (s * 8 + srow) * ROWB + (256 + IN_W * pb + scol) * 4;
        if constexpr (IS_L0) {
            if (u < BC / 2 * 13) *(unsigned*)dst = pack_hilo(pf_f[s]);
        } else {
            *(uint4*)dst = pf_u[s];
        }
    };

    // prologue: stage input(0) for both streams; preload input(1)
    if (warp >= 8) {
        prefetch(0, 0); stage(0, 0);
        prefetch(1, 0); stage(1, 0);
        prefetch(0, 1);
    }
    __syncthreads();
    cluster.sync();                                 // zeros + inputs + mbars visible

    for (int phi = 0; phi < 2 * T_STEPS; ++phi) {
        const int t = phi >> 1, s = phi & 1, p = t & 1;

        // deferred cluster wait: h(t) of stream s (arrived 2 phases ago)
        if (t > 0) mbar_wait_cl(mb_u + 8 * s, (unsigned)((t - 1) & 1));

        // ---- GEMM: D[128][8], 3-pass split-precision bf16 HMMA ----
        float acc[2][4];
        #pragma unroll
        for (int mt = 0; mt < 2; ++mt)
            #pragma unroll
            for (int r = 0; r < 4; ++r) acc[mt][r] = 0.0f;

        const char* Brow = base + (s * 8 + lg) * ROWB;
        #pragma unroll
        for (int sk = 0; sk < KS; ++sk) {
            const int k0 = (kq * KS + sk) * 16;
            const int w0 = (k0 < 128) ? (k0 + 128 * p) : (256 + IN_W * p + (k0 - 128));
            const char* pb = Brow + (w0 + la * 2) * 4;
            uint2 q0 = *(const uint2*)(pb);
            uint2 q1 = *(const uint2*)(pb + 32);
            unsigned bh[2], bl[2];
            bh[0] = __byte_perm(q0.x, q0.y, 0x5410);
            bl[0] = __byte_perm(q0.x, q0.y, 0x7632);
            bh[1] = __byte_perm(q1.x, q1.y, 0x5410);
            bl[1] = __byte_perm(q1.x, q1.y, 0x7632);
            #pragma unroll
            for (int mt = 0; mt < 2; ++mt) {
                mma_bf16(acc[mt], Ahi[mt][sk], bh);
                mma_bf16(acc[mt], Ahi[mt][sk], bl);
                mma_bf16(acc[mt], Alo[mt][sk], bh);
            }
        }

        // ---- store partials (stream-private buffer; conflict-free) ----
        {
            float* pq = part + s * PHALF + kq * (8 * PSTR);
            #pragma unroll
            for (int mt = 0; mt < 2; ++mt) {
                const int m0 = (mtp * 2 + mt) * 16 + lg;
                pq[(2 * la) * PSTR + m0]           = acc[mt][0];
                pq[(2 * la + 1) * PSTR + m0]       = acc[mt][1];
                pq[(2 * la) * PSTR + m0 + 8]       = acc[mt][2];
                pq[(2 * la + 1) * PSTR + m0 + 8]   = acc[mt][3];
            }
        }
        __syncthreads();

        if (warp < 8) {
            // ---- pointwise: combine 4 partials + bias, update, push h ----
            float g0 = bi0, g1 = bi1, g2 = bi2, g3 = bi3;
            #pragma unroll
            for (int q = 0; q < 4; ++q) {
                const float* pp = part + s * PHALF + q * (8 * PSTR) + warp * PSTR + lane;
                g0 += pp[0]; g1 += pp[32]; g2 += pp[64]; g3 += pp[96];
            }
            float c = sig_f(g1) * creg[s] + sig_f(g0) * tanh_f(g2);
            creg[s] = c;
            float h = sig_f(g3) * tanh_f(c);
            unsigned word = pack_hilo(h);
            if (t + 1 < T_STEPS) {
                const unsigned off =
                    (unsigned)((s * 8 + warp) * ROWB + (128 * (p ^ 1) + 32 * rank + lane) * 4);
                #pragma unroll
                for (int d = 0; d < CLUSTER_N; ++d) stc_u32(peer_base[d] + off, word);
            }
            if constexpr (IS_L0) {
                g_h1[((size_t)t * BATCH + B0 + s * 8 + warp) * 128 + 32 * rank + lane] = word;
            } else {
                if (t == T_STEPS - 1)
                    g_h2last[(B0 + s * 8 + warp) * 128 + 32 * rank + lane] = h;
            }
            // per-warp release-arrive on all peers (orders this warp's pushes)
            if (t + 1 < T_STEPS && lane == 0) {
                #pragma unroll
                for (int d = 0; d < CLUSTER_N; ++d)
                    mbar_arrive_rank(mb_u + 8 * s, (unsigned)d);
            }
        } else {
            // ---- staging: input(t+1) from regs; prefetch input(t+2) ----
            if (t + 1 < T_STEPS) stage(s, (t + 1) & 1);
            if (t + 2 < T_STEPS || (t + 1 < T_STEPS && s == 0)) {
                const int tn = t + 1 + s;      // s=0 -> (s=1,t+1); s=1 -> (s=0,t+2)
                if (tn < T_STEPS) prefetch(s ^ 1, tn);
            }
        }
    }

    cluster.sync();   // keep SMEM alive for in-flight peer stores
}

__global__ void fc_kernel(const float* __restrict__ Wfc, const float* __restrict__ bfc,
                          float* __restrict__ out)
{
    __shared__ float w[4][128];
    int tid = threadIdx.x;
    for (int idx = tid; idx < 512; idx += 128) w[idx >> 7][idx & 127] = Wfc[idx];
    __syncthreads();
    int b = blockIdx.x * 128 + tid;
    float s[4];
    #pragma unroll
    for (int cc = 0; cc < 4; ++cc) s[cc] = bfc[cc];
    #pragma unroll 4
    for (int k = 0; k < 128; ++k) {
        float h = g_h2last[b * 128 + k];
        #pragma unroll
        for (int cc = 0; cc < 4; ++cc) s[cc] = fmaf(h, w[cc][k], s[cc]);
    }
    #pragma unroll
    for (int cc = 0; cc < 4; ++cc) out[b * 4 + cc] = s[cc];
}

extern "C" void kernel_launch(void* const* d_in, const int* in_sizes, int n_in,
                              void* d_out, int out_size)
{
    (void)in_sizes; (void)n_in; (void)out_size;
    const float* x    = (const float*)d_in[0];
    const float* Wih0 = (const float*)d_in[1];
    const float* Whh0 = (const float*)d_in[2];
    const float* bih0 = (const float*)d_in[3];
    const float* bhh0 = (const float*)d_in[4];
    const float* Wih1 = (const float*)d_in[5];
    const float* Whh1 = (const float*)d_in[6];
    const float* bih1 = (const float*)d_in[7];
    const float* bhh1 = (const float*)d_in[8];
    const float* Wfc  = (const float*)d_in[9];
    const float* bfc  = (const float*)d_in[10];
    float* out = (float*)d_out;

    // layer0: K_PAD=192 (h 0..127, x at 128..140), KS=3
    // layer1: K_PAD=256 (h2 0..127, h1 128..255),  KS=4
    auto smem_bytes = [](int kpad) {
        int rw = 256 + 2 * (kpad - 128);
        int rowb = rw * 4 + 16;
        return BC * rowb + 2 * (32 * PSTR) * 4 + 512 + 32 + 256;
    };
    const int smem0 = smem_bytes(192);
    const int smem1 = smem_bytes(256);

    cudaFuncSetAttribute((const void*)lstm_scan<13, 192, 3, true>,
                         cudaFuncAttributeMaxDynamicSharedMemorySize, smem0);
    cudaFuncSetAttribute((const void*)lstm_scan<128, 256, 4, false>,
                         cudaFuncAttributeMaxDynamicSharedMemorySize, smem1);

    lstm_scan<13, 192, 3, true><<<NCLUSTERS * CLUSTER_N, THREADS, smem0>>>(
        Wih0, Whh0, bih0, bhh0, x);
    lstm_scan<128, 256, 4, false><<<NCLUSTERS * CLUSTER_N, THREADS, smem1>>>(
        Wih1, Whh1, bih1, bhh1, nullptr);
    fc_kernel<<<4, 128>>>(Wfc, bfc, out);
}

// round 17
// speedup vs baseline: 1.8740x; 1.8740x over previous
#include <cuda_runtime.h>
#include <cooperative_groups.h>
#include <cuda_bf16.h>
#include <stdint.h>

namespace cg = cooperative_groups;

#define T_STEPS  2000
#define BATCH    512
#define CLUSTER_N 4
#define NCLUSTERS 32
#define THREADS  512
#define BC       16      // batch rows per cluster
#define PSTR     132     // partial row stride (words): conflict-free STS/LDS
#define PHALF    (BC * PSTR)

typedef unsigned long long ull;

// layer0 hidden sequence as packed words (bf16 hi | bf16 lo << 16)
__device__ unsigned g_h1[(size_t)T_STEPS * BATCH * 128];
__device__ float    g_h2last[BATCH * 128];

// ---------- activations ----------
__device__ __forceinline__ float tanh_f(float x){float y;asm("tanh.approx.f32 %0,%1;":"=f"(y):"f"(x));return y;}
__device__ __forceinline__ float sig_f(float x){ return 0.5f*tanh_f(0.5f*x) + 0.5f; }

// ---------- mbarrier / cluster helpers (R10/R13-proven) ----------
__device__ __forceinline__ void mbar_init(unsigned a, unsigned cnt) {
    asm volatile("mbarrier.init.shared.b64 [%0], %1;" :: "r"(a), "r"(cnt) : "memory");
}
__device__ __forceinline__ void mbar_arrive_rank(unsigned a, unsigned rk) {
    asm volatile(
        "{\n\t.reg .b32 ra;\n\t"
        "mapa.shared::cluster.u32 ra, %0, %1;\n\t"
        "mbarrier.arrive.release.cluster.shared::cluster.b64 _, [ra];\n\t}"
        :: "r"(a), "r"(rk) : "memory");
}
__device__ __forceinline__ void mbar_wait_cl(unsigned a, unsigned par) {
    asm volatile(
        "{\n\t.reg .pred P;\n\tLW%=:\n\t"
        "mbarrier.try_wait.parity.acquire.cluster.shared::cta.b64 P, [%0], %1, 0x989680;\n\t"
        "@P bra LD%=;\n\tbra LW%=;\n\tLD%=:\n\t}"
        :: "r"(a), "r"(par) : "memory");
}
__device__ __forceinline__ unsigned mapa_rk(unsigned a, unsigned rk) {
    unsigned r; asm("mapa.shared::cluster.u32 %0, %1, %2;" : "=r"(r) : "r"(a), "r"(rk));
    return r;
}
__device__ __forceinline__ void stc_u32(unsigned a, unsigned v) {
    asm volatile("st.shared::cluster.u32 [%0], %1;" :: "r"(a), "r"(v) : "memory");
}

// ---------- bf16 HMMA m16n8k16 ----------
__device__ __forceinline__ void mma_bf16(float* d, const unsigned* a, const unsigned* b) {
    asm volatile(
        "mma.sync.aligned.m16n8k16.row.col.f32.bf16.bf16.f32 "
        "{%0,%1,%2,%3}, {%4,%5,%6,%7}, {%8,%9}, {%0,%1,%2,%3};"
        : "+f"(d[0]), "+f"(d[1]), "+f"(d[2]), "+f"(d[3])
        : "r"(a[0]), "r"(a[1]), "r"(a[2]), "r"(a[3]), "r"(b[0]), "r"(b[1]));
}
__device__ __forceinline__ unsigned pack2(float x, float y) {
    __nv_bfloat162 v = __floats2bfloat162_rn(x, y);
    return *reinterpret_cast<unsigned*>(&v);
}
__device__ __forceinline__ unsigned pack_hilo(float v) {
    __nv_bfloat16 hb = __float2bfloat16(v);
    float hf = __bfloat162float(hb);
    __nv_bfloat16 lb = __float2bfloat16(v - hf);
    return (unsigned)__bfloat16_as_ushort(hb) | ((unsigned)__bfloat16_as_ushort(lb) << 16);
}

// 3-pass split-precision GEMM over one K half. acc[nt][4] for one m16 tile.
template<int NKS>
__device__ __forceinline__ void gemm_half(float (*acc)[4],
    const unsigned (*Ahi)[4], const unsigned (*Alo)[4],
    const char* brow0, const char* brow1, int wbase)
{
    #pragma unroll
    for (int sk = 0; sk < NKS; ++sk) {
        const int bo = (wbase + sk * 16) * 4;
        #pragma unroll
        for (int nt = 0; nt < 2; ++nt) {
            const char* pr = (nt ? brow1 : brow0) + bo;
            uint2 q0 = *(const uint2*)(pr);
            uint2 q1 = *(const uint2*)(pr + 32);
            unsigned bh[2], bl[2];
            bh[0] = __byte_perm(q0.x, q0.y, 0x5410);
            bl[0] = __byte_perm(q0.x, q0.y, 0x7632);
            bh[1] = __byte_perm(q1.x, q1.y, 0x5410);
            bl[1] = __byte_perm(q1.x, q1.y, 0x7632);
            mma_bf16(acc[nt], Ahi[sk], bh);
            mma_bf16(acc[nt], Ahi[sk], bl);
            mma_bf16(acc[nt], Alo[sk], bh);
        }
    }
}

// =====================================================================
// R13 skeleton (one cluster rendezvous per step), shortened chain.
// Cluster of 4 CTAs = 16 batch rows. CTA rank r owns gate-interleaved
// cols [32r,32r+32) of every gate -> pointwise fully CTA-local; h pushed
// to peers as ONE packed u32 (hi|lo bf16) via DSMEM.
// B row (u32 words): [h p0:128][h p1:128][in p0:IN_W][in p1:IN_W].
// GEMM: D[128][16] bf16 HMMA, 3 passes (Whi*hhi + Whi*hlo + Wlo*hhi),
// A step-invariant in registers. 16 warps = 8 m-tiles x 2 K-halves.
// K-half 1 is the pure-INPUT range -> those warps skip the cluster wait
// and compute during the rendezvous; all meet at __syncthreads.
// Partials: 2 stream buffers (kh), combined in the pointwise pass.
// =====================================================================
template<int K_IN, int IN_W, int KS0, int KS1, bool IS_L0>
__global__ __launch_bounds__(THREADS, 1) __cluster_dims__(CLUSTER_N, 1, 1)
void lstm_scan(const float* __restrict__ W_ih, const float* __restrict__ W_hh,
               const float* __restrict__ b_ih, const float* __restrict__ b_hh,
               const float* __restrict__ x)
{
    constexpr int RW    = 256 + 2 * IN_W;          // words per B row
    constexpr int ROWB  = RW * 4 + 16;             // bytes per B row
    constexpr int OPART = BC * ROWB;
    constexpr int OBIAS = OPART + 2 * PHALF * 4;
    constexpr int OMB   = OBIAS + 512;

    extern __shared__ char smraw[];
    char* base = (char*)(((uintptr_t)smraw + 127) & ~(uintptr_t)127);
    float* part   = (float*)(base + OPART);
    float* bias_s = (float*)(base + OBIAS);
    const unsigned base_u = (unsigned)__cvta_generic_to_shared(base);
    const unsigned mb_u   = base_u + OMB;

    cg::cluster_group cluster = cg::this_cluster();
    const int rank = (int)cluster.block_rank();
    const int tid  = threadIdx.x;
    const int warp = tid >> 5, lane = tid & 31;
    const int tg = lane >> 2, la = lane & 3;
    const int mtile = warp >> 1, kh = warp & 1;
    const int cid = blockIdx.x / CLUSTER_N;
    const int B0  = cid * BC;

    // ---- one-time: weight fragments (hi/lo) into registers ----
    unsigned Ahi[KS0][4], Alo[KS0][4];
    const int myks = kh ? KS1 : KS0;
    #pragma unroll
    for (int s = 0; s < KS0; ++s) {
        #pragma unroll
        for (int r = 0; r < 4; ++r) {
            float v0 = 0.0f, v1 = 0.0f;
            if (s < myks) {
                int m = mtile * 16 + tg + ((r & 1) ? 8 : 0);
                int k = (kh ? 128 + s * 16 : s * 16) + la * 2 + ((r & 2) ? 8 : 0);
                int grow = (m >> 5) * 128 + 32 * rank + (m & 31);
                if (k < 128) v0 = W_hh[grow * 128 + k];
                else if (k - 128 < K_IN) v0 = W_ih[grow * K_IN + (k - 128)];
                if (k + 1 < 128) v1 = W_hh[grow * 128 + k + 1];
                else if (k + 1 - 128 < K_IN) v1 = W_ih[grow * K_IN + (k + 1 - 128)];
            }
            float h0 = __bfloat162float(__float2bfloat16(v0));
            float h1 = __bfloat162float(__float2bfloat16(v1));
            Ahi[s][r] = pack2(h0, h1);
            Alo[s][r] = pack2(v0 - h0, v1 - h1);
        }
    }

    // zero the whole B tile (h(0)=0, pad stays 0)
    for (int i = tid * 4; i < BC * ROWB; i += THREADS * 4)
        *(unsigned*)(base + i) = 0u;
    if (tid < 128) {
        int g = tid >> 5, c = tid & 31;
        bias_s[tid] = b_ih[g * 128 + 32 * rank + c] + b_hh[g * 128 + 32 * rank + c];
    }
    if (tid == 0) mbar_init(mb_u, 4);
    __syncthreads();

    unsigned peer_base[CLUSTER_N];
    #pragma unroll
    for (int d = 0; d < CLUSTER_N; ++d) peer_base[d] = mapa_rk(base_u, d);

    // B fragment row pointers (n rows: tg and 8+tg), la offset folded in
    const char* brow0 = base + tg * ROWB + la * 8;
    const char* brow1 = base + (8 + tg) * ROWB + la * 8;

    // pointwise: 1 element/thread, row = warp, col = lane
    float creg = 0.0f;
    const float bi0 = bias_s[lane], bi1 = bias_s[32 + lane],
                bi2 = bias_s[64 + lane], bi3 = bias_s[96 + lane];

    // staging ids
    int srow = 0, scol = 0;
    if constexpr (IS_L0) { srow = tid / 13; scol = tid - srow * 13; }
    else                 { srow = tid >> 5; scol = (tid & 31) * 4; }

    float pf_f = 0.0f; uint4 pf_u = {0, 0, 0, 0};
    auto prefetch = [&](int t) {
        if constexpr (IS_L0) {
            if (tid < BC * 13)
                pf_f = x[((size_t)(B0 + srow) * T_STEPS + t) * 13 + scol];
        } else {
            pf_u = *(const uint4*)&g_h1[((size_t)t * BATCH + B0 + srow) * 128 + scol];
        }
    };
    auto stage = [&](int pb) {
        char* dst = base + srow * ROWB + (256 + IN_W * pb + scol) * 4;
        if constexpr (IS_L0) {
            if (tid < BC * 13) *(unsigned*)dst = pack_hilo(pf_f);
        } else {
            *(uint4*)dst = pf_u;
        }
    };

    prefetch(0);
    stage(0);
    __syncthreads();
    cluster.sync();                          // zeros + input(0) + mbar visible

    for (int t = 0; t < T_STEPS; ++t) {
        const int p = t & 1;
        if (t + 1 < T_STEPS) prefetch(t + 1);

        // ---- GEMM (kh=0 waits for the cluster rendezvous; kh=1 doesn't) ----
        float acc[2][4];
        #pragma unroll
        for (int nt = 0; nt < 2; ++nt)
            #pragma unroll
            for (int r = 0; r < 4; ++r) acc[nt][r] = 0.0f;

        if (kh == 0) {
            if (t > 0) mbar_wait_cl(mb_u, (unsigned)((t - 1) & 1));
            gemm_half<KS0>(acc, Ahi, Alo, brow0, brow1, 128 * p);
        } else {
            gemm_half<KS1>(acc, Ahi, Alo, brow0, brow1, 256 + IN_W * p);
        }

        // ---- store partials (per-kh buffer; conflict-free by PSTR=132) ----
        {
            float* pq = part + kh * PHALF;
            const int m0 = mtile * 16 + tg;
            #pragma unroll
            for (int nt = 0; nt < 2; ++nt) {
                const int n0 = nt * 8 + 2 * la;
                pq[n0 * PSTR + m0]           = acc[nt][0];
                pq[(n0 + 1) * PSTR + m0]     = acc[nt][1];
                pq[n0 * PSTR + m0 + 8]       = acc[nt][2];
                pq[(n0 + 1) * PSTR + m0 + 8] = acc[nt][3];
            }
        }
        if (t + 1 < T_STEPS) stage(p ^ 1);   // input(t+1): disjoint parity region
        __syncthreads();

        // ---- pointwise: combine 2 partials + bias, update, push h ----
        {
            const float* pp = part + warp * PSTR + lane;
            float g0 = bi0 + pp[0]  + pp[PHALF];
            float g1 = bi1 + pp[32] + pp[PHALF + 32];
            float g2 = bi2 + pp[64] + pp[PHALF + 64];
            float g3 = bi3 + pp[96] + pp[PHALF + 96];
            float c = sig_f(g1) * creg + sig_f(g0) * tanh_f(g2);
            creg = c;
            float h = sig_f(g3) * tanh_f(c);
            unsigned word = pack_hilo(h);
            if (t + 1 < T_STEPS) {
                const unsigned off =
                    (unsigned)(warp * ROWB + (128 * (p ^ 1) + 32 * rank + lane) * 4);
                #pragma unroll
                for (int d = 0; d < CLUSTER_N; ++d) stc_u32(peer_base[d] + off, word);
            }
            if constexpr (IS_L0) {
                g_h1[((size_t)t * BATCH + B0 + warp) * 128 + 32 * rank + lane] = word;
            } else {
                if (t == T_STEPS - 1)
                    g_h2last[(B0 + warp) * 128 + 32 * rank + lane] = h;
            }
        }
        __syncthreads();                     // all pushes issued CTA-wide
        if (t + 1 < T_STEPS && tid < 4)
            mbar_arrive_rank(mb_u, (unsigned)tid);
    }

    cluster.sync();   // keep SMEM alive for in-flight peer stores
}

__global__ void fc_kernel(const float* __restrict__ Wfc, const float* __restrict__ bfc,
                          float* __restrict__ out)
{
    __shared__ float w[4][128];
    int tid = threadIdx.x;
    for (int idx = tid; idx < 512; idx += 128) w[idx >> 7][idx & 127] = Wfc[idx];
    __syncthreads();
    int b = blockIdx.x * 128 + tid;
    float s[4];
    #pragma unroll
    for (int cc = 0; cc < 4; ++cc) s[cc] = bfc[cc];
    #pragma unroll 4
    for (int k = 0; k < 128; ++k) {
        float h = g_h2last[b * 128 + k];
        #pragma unroll
        for (int cc = 0; cc < 4; ++cc) s[cc] = fmaf(h, w[cc][k], s[cc]);
    }
    #pragma unroll
    for (int cc = 0; cc < 4; ++cc) out[b * 4 + cc] = s[cc];
}

extern "C" void kernel_launch(void* const* d_in, const int* in_sizes, int n_in,
                              void* d_out, int out_size)
{
    (void)in_sizes; (void)n_in; (void)out_size;
    const float* x    = (const float*)d_in[0];
    const float* Wih0 = (const float*)d_in[1];
    const float* Whh0 = (const float*)d_in[2];
    const float* bih0 = (const float*)d_in[3];
    const float* bhh0 = (const float*)d_in[4];
    const float* Wih1 = (const float*)d_in[5];
    const float* Whh1 = (const float*)d_in[6];
    const float* bih1 = (const float*)d_in[7];
    const float* bhh1 = (const float*)d_in[8];
    const float* Wfc  = (const float*)d_in[9];
    const float* bfc  = (const float*)d_in[10];
    float* out = (float*)d_out;

    // layer0: IN_W=16 (x, 13 padded), KS0=8 (h k0..127), KS1=1 (x k128..143)
    // layer1: IN_W=128 (h1),          KS0=8,             KS1=8
    auto smem_bytes = [](int in_w) {
        int rw = 256 + 2 * in_w;
        return BC * (rw * 4 + 16) + 2 * PHALF * 4 + 512 + 16 + 256;
    };
    const int smem0 = smem_bytes(16);
    const int smem1 = smem_bytes(128);

    cudaFuncSetAttribute((const void*)lstm_scan<13, 16, 8, 1, true>,
                         cudaFuncAttributeMaxDynamicSharedMemorySize, smem0);
    cudaFuncSetAttribute((const void*)lstm_scan<128, 128, 8, 8, false>,
                         cudaFuncAttributeMaxDynamicSharedMemorySize, smem1);

    lstm_scan<13, 16, 8, 1, true><<<NCLUSTERS * CLUSTER_N, THREADS, smem0>>>(
        Wih0, Whh0, bih0, bhh0, x);
    lstm_scan<128, 128, 8, 8, false><<<NCLUSTERS * CLUSTER_N, THREADS, smem1>>>(
        Wih1, Whh1, bih1, bhh1, nullptr);
    fc_kernel<<<4, 128>>>(Wfc, bfc, out);
}